// round 11
// baseline (speedup 1.0000x reference)
#include <cuda_runtime.h>
#include <cuda_fp16.h>
#include <cstdint>
#include <math.h>

#define BATCH 8192
#define INDIM 1024
#define HID   2048
#define KTOT  3072
#define NTOT  8192

#define BM 128
#define BN 256
#define BK 64
#define STAGES 3
#define THREADS 256
#define A_BYTES (BM * BK * 2)               // 16384
#define B_BYTES (BN * BK * 2)               // 32768
#define STAGE_BYTES (A_BYTES + B_BYTES)     // 49152
#define SMEM_BYTES (STAGES * STAGE_BYTES)   // 147456
#define STG_LD 264                          // fp32 staging row stride (256 + 8 pad)
// STG_BYTES = 128 * 264 * 4 = 135168 <= SMEM_BYTES

__device__ __half g_xh [(size_t)BATCH * KTOT];   // concat(x,h) fp16
__device__ __half g_wt [(size_t)NTOT  * KTOT];   // gates weights, rows = h*4+g, K-major
__device__ __half g_wrt[(size_t)HID   * INDIM];  // residual weights, K-major
__device__ float  g_xres[(size_t)BATCH * HID];   // residual preacts

__device__ __forceinline__ uint32_t smem_u32(const void* p) {
    uint32_t a;
    asm("{ .reg .u64 t; cvta.to.shared.u64 t, %1; cvt.u32.u64 %0, t; }" : "=r"(a) : "l"(p));
    return a;
}
__device__ __forceinline__ uint32_t swz(uint32_t o) { return o ^ ((o >> 3) & 0x70); }
__device__ __forceinline__ void cp16(uint32_t dst, const void* src) {
    asm volatile("cp.async.cg.shared.global [%0], [%1], 16;" :: "r"(dst), "l"(src));
}
#define CP_COMMIT() asm volatile("cp.async.commit_group;" ::: "memory")
#define CP_WAIT(n)  asm volatile("cp.async.wait_group %0;" :: "n"(n) : "memory")

__device__ __forceinline__ void ldsm_x4(uint32_t* d, uint32_t addr) {
    asm volatile("ldmatrix.sync.aligned.m8n8.x4.shared.b16 {%0,%1,%2,%3}, [%4];"
        : "=r"(d[0]), "=r"(d[1]), "=r"(d[2]), "=r"(d[3]) : "r"(addr));
}
__device__ __forceinline__ void mma16816(float* c, const uint32_t* a, const uint32_t* b) {
    asm volatile(
        "mma.sync.aligned.m16n8k16.row.col.f32.f16.f16.f32 "
        "{%0,%1,%2,%3}, {%4,%5,%6,%7}, {%8,%9}, {%0,%1,%2,%3};"
        : "+f"(c[0]), "+f"(c[1]), "+f"(c[2]), "+f"(c[3])
        : "r"(a[0]), "r"(a[1]), "r"(a[2]), "r"(a[3]), "r"(b[0]), "r"(b[1]));
}
__device__ __forceinline__ float fsigmoid(float x) { return 1.0f / (1.0f + __expf(-x)); }
__device__ __forceinline__ float ftanh(float x)    { return 2.0f / (1.0f + __expf(-2.0f * x)) - 1.0f; }

// ---------------- pre-passes ----------------
__global__ void prep_xh(const float* __restrict__ x, const float* __restrict__ h) {
    int k = blockIdx.x * 256 + threadIdx.x;
    int b = blockIdx.y;
    float v = (k < INDIM) ? x[(size_t)b * INDIM + k]
                          : h[(size_t)b * HID + (k - INDIM)];
    g_xh[(size_t)b * KTOT + k] = __float2half_rn(v);
}

// W_gates[g][k][h] -> g_wt[(h*4+g)][k]  (gate-interleaved rows)
__global__ void prep_wg(const float* __restrict__ Wg) {
    __shared__ float t[32][33];
    int k0 = blockIdx.x * 32, h0 = blockIdx.y * 32, g = blockIdx.z;
    const float* src = Wg + ((size_t)g * KTOT + k0) * HID + h0;
#pragma unroll
    for (int i = 0; i < 4; i++)
        t[threadIdx.y + 8 * i][threadIdx.x] = src[(size_t)(threadIdx.y + 8 * i) * HID + threadIdx.x];
    __syncthreads();
#pragma unroll
    for (int i = 0; i < 4; i++) {
        int hh = threadIdx.y + 8 * i;
        g_wt[((size_t)((h0 + hh) * 4 + g)) * KTOT + k0 + threadIdx.x] =
            __float2half_rn(t[threadIdx.x][hh]);
    }
}

__global__ void prep_wr(const float* __restrict__ Wr) {
    __shared__ float t[32][33];
    int k0 = blockIdx.x * 32, h0 = blockIdx.y * 32;
    const float* src = Wr + (size_t)k0 * HID + h0;
#pragma unroll
    for (int i = 0; i < 4; i++)
        t[threadIdx.y + 8 * i][threadIdx.x] = src[(size_t)(threadIdx.y + 8 * i) * HID + threadIdx.x];
    __syncthreads();
#pragma unroll
    for (int i = 0; i < 4; i++) {
        int hh = threadIdx.y + 8 * i;
        g_wrt[((size_t)(h0 + hh)) * INDIM + k0 + threadIdx.x] =
            __float2half_rn(t[threadIdx.x][hh]);
    }
}

// ---------------- stage loader (R7 layout: 256 threads) ----------------
__device__ __forceinline__ void load_stage(uint32_t sA, uint32_t sB,
                                           const __half* __restrict__ A,
                                           const __half* __restrict__ Bw,
                                           int m0, int n0, int k0,
                                           int lda, int ldb, int tid) {
#pragma unroll
    for (int it = 0; it < 4; it++) {             // A: 128 rows x 8 x 16B
        int i = tid + it * THREADS;
        int r = i >> 3, cg = i & 7;
        uint32_t sw = swz((uint32_t)(r * 128 + cg * 16));
        cp16(sA + sw, A + (size_t)(m0 + r) * lda + k0 + cg * 8);
    }
#pragma unroll
    for (int it = 0; it < 8; it++) {             // B: 256 rows x 8 x 16B
        int i = tid + it * THREADS;
        int r = i >> 3, cg = i & 7;
        uint32_t sw = swz((uint32_t)(r * 128 + cg * 16));
        cp16(sB + sw, Bw + (size_t)(n0 + r) * ldb + k0 + cg * 8);
    }
}

// ---------------- mainloop macro-body shared by both kernels ----------------
#define GEMM_MAINLOOP(K_, LDA_)                                                          \
    float acc[4][8][4];                                                                  \
    _Pragma("unroll")                                                                    \
    for (int mi = 0; mi < 4; mi++)                                                       \
        _Pragma("unroll")                                                                \
        for (int ni = 0; ni < 8; ni++)                                                   \
            _Pragma("unroll")                                                            \
            for (int e = 0; e < 4; e++) acc[mi][ni][e] = 0.0f;                           \
    _Pragma("unroll")                                                                    \
    for (int s = 0; s < STAGES - 1; s++) {                                               \
        load_stage(sb + s * STAGE_BYTES, sb + s * STAGE_BYTES + A_BYTES,                 \
                   A, Bw, m0, n0, s * BK, LDA_, K_, tid);                                \
        CP_COMMIT();                                                                     \
    }                                                                                    \
    const int nch = (K_) / BK;                                                           \
    for (int c = 0; c < nch; c++) {                                                      \
        CP_WAIT(STAGES - 2);                                                             \
        __syncthreads();                                                                 \
        int cl = c + STAGES - 1;                                                         \
        if (cl < nch) {                                                                  \
            int s = cl % STAGES;                                                         \
            load_stage(sb + s * STAGE_BYTES, sb + s * STAGE_BYTES + A_BYTES,             \
                       A, Bw, m0, n0, cl * BK, LDA_, K_, tid);                           \
        }                                                                                \
        CP_COMMIT();                                                                     \
        uint32_t sA = sb + (c % STAGES) * STAGE_BYTES;                                   \
        uint32_t sB = sA + A_BYTES;                                                      \
        _Pragma("unroll")                                                                \
        for (int ks = 0; ks < 4; ks++) {                                                 \
            uint32_t af[4][4];                                                           \
            {                                                                            \
                int ra = lane & 15;                                                      \
                int kg = ks * 2 + (lane >> 4);                                           \
                _Pragma("unroll")                                                        \
                for (int mi = 0; mi < 4; mi++) {                                         \
                    uint32_t off = (uint32_t)((wm * 64 + mi * 16 + ra) * 128 + kg * 16); \
                    ldsm_x4(af[mi], sA + swz(off));                                      \
                }                                                                        \
            }                                                                            \
            uint32_t bf[8][2];                                                           \
            {                                                                            \
                int rb = (lane & 7) + ((lane >> 4) << 3);                                \
                int kg = ks * 2 + ((lane >> 3) & 1);                                     \
                _Pragma("unroll")                                                        \
                for (int nq = 0; nq < 4; nq++) {                                         \
                    uint32_t t[4];                                                       \
                    uint32_t off = (uint32_t)((wn * 64 + nq * 16 + rb) * 128 + kg * 16); \
                    ldsm_x4(t, sB + swz(off));                                           \
                    bf[nq * 2][0] = t[0]; bf[nq * 2][1] = t[1];                          \
                    bf[nq * 2 + 1][0] = t[2]; bf[nq * 2 + 1][1] = t[3];                  \
                }                                                                        \
            }                                                                            \
            _Pragma("unroll")                                                            \
            for (int mi = 0; mi < 4; mi++)                                               \
                _Pragma("unroll")                                                        \
                for (int ni = 0; ni < 8; ni++)                                           \
                    mma16816(acc[mi][ni], af[mi], bf[ni]);                               \
        }                                                                                \
    }

// ---------------- residual GEMM (plain store) ----------------
__global__ void __launch_bounds__(THREADS, 1)
gemm_res(const __half* __restrict__ A, const __half* __restrict__ Bw,
         float* __restrict__ C) {
    extern __shared__ char smem[];
    uint32_t sb = smem_u32(smem);
    const int tid = threadIdx.x, lane = tid & 31, wid = tid >> 5;
    const int wm = wid & 1;
    const int wn = wid >> 1;
    const int m0 = blockIdx.x * BM;
    const int n0 = blockIdx.y * BN;

    GEMM_MAINLOOP(INDIM, KTOT)

    const int gid = lane >> 2, tq = lane & 3;
#pragma unroll
    for (int mi = 0; mi < 4; mi++) {
#pragma unroll
        for (int ni = 0; ni < 8; ni++) {
            int m = m0 + wm * 64 + mi * 16 + gid;
            int n = n0 + wn * 64 + ni * 8 + tq * 2;
            *(float2*)&C[(size_t)m * HID + n]       = make_float2(acc[mi][ni][0], acc[mi][ni][1]);
            *(float2*)&C[(size_t)(m + 8) * HID + n] = make_float2(acc[mi][ni][2], acc[mi][ni][3]);
        }
    }
}

// ---------------- gates GEMM + fused LSTM epilogue ----------------
__global__ void __launch_bounds__(THREADS, 1)
gemm_gates(const __half* __restrict__ A, const __half* __restrict__ Bw,
           const float* __restrict__ c_prev, const float* __restrict__ bg,
           const float* __restrict__ br, const float* __restrict__ xres,
           float* __restrict__ out) {
    extern __shared__ char smem[];
    uint32_t sb = smem_u32(smem);
    const int tid = threadIdx.x, lane = tid & 31, wid = tid >> 5;
    const int wm = wid & 1;
    const int wn = wid >> 1;
    const int m0 = blockIdx.x * BM;
    const int n0 = blockIdx.y * BN;

    GEMM_MAINLOOP(KTOT, KTOT)

    // stage accumulators to smem (pipeline smem is dead now)
    CP_WAIT(0);
    __syncthreads();
    float* stg = (float*)smem;
    const int gid = lane >> 2, tq = lane & 3;
#pragma unroll
    for (int mi = 0; mi < 4; mi++) {
#pragma unroll
        for (int ni = 0; ni < 8; ni++) {
            int r = wm * 64 + mi * 16 + gid;
            int n = wn * 64 + ni * 8 + tq * 2;
            *(float2*)&stg[r * STG_LD + n]       = make_float2(acc[mi][ni][0], acc[mi][ni][1]);
            *(float2*)&stg[(r + 8) * STG_LD + n] = make_float2(acc[mi][ni][2], acc[mi][ni][3]);
        }
    }
    __syncthreads();

    const int h0 = n0 >> 2;          // 64 h-columns per CTA (cols = h*4+g interleave)
#pragma unroll 4
    for (int it = 0; it < 32; it++) {
        int cell = tid + it * THREADS;     // 0..8191
        int r  = cell >> 6;                // row 0..127
        int hh = cell & 63;                // local h
        float4 gv = *(float4*)&stg[r * STG_LD + hh * 4];   // (i,f,o,c) preacts
        int hg = h0 + hh;
        int m  = m0 + r;

        float iv = fsigmoid(gv.x + bg[hg]);
        float fv = fsigmoid(gv.y + bg[2048 + hg]);
        float ov = fsigmoid(gv.z + bg[4096 + hg]);
        float ch = ftanh(gv.w + bg[6144 + hg]);

        float ct = fv * c_prev[(size_t)m * HID + hg] + iv * ch;
        float xr = xres[(size_t)m * HID + hg] + br[hg];
        float ht = ov * ftanh(ct) + xr;

        out[(size_t)m * HID + hg] = ht;
        out[(size_t)BATCH * HID + (size_t)m * HID + hg] = ct;
    }
}

extern "C" void kernel_launch(void* const* d_in, const int* in_sizes, int n_in,
                              void* d_out, int out_size) {
    const float* x  = (const float*)d_in[0];
    const float* h  = (const float*)d_in[1];
    const float* c  = (const float*)d_in[2];
    const float* Wg = (const float*)d_in[3];
    const float* bg = (const float*)d_in[4];
    const float* Wr = (const float*)d_in[5];
    const float* br = (const float*)d_in[6];
    float* out = (float*)d_out;

    prep_xh<<<dim3(KTOT / 256, BATCH), 256>>>(x, h);
    prep_wg<<<dim3(KTOT / 32, HID / 32, 4), dim3(32, 8)>>>(Wg);
    prep_wr<<<dim3(INDIM / 32, HID / 32), dim3(32, 8)>>>(Wr);

    cudaFuncSetAttribute(gemm_res,   cudaFuncAttributeMaxDynamicSharedMemorySize, SMEM_BYTES);
    cudaFuncSetAttribute(gemm_gates, cudaFuncAttributeMaxDynamicSharedMemorySize, SMEM_BYTES);

    __half* xh;  cudaGetSymbolAddress((void**)&xh,  g_xh);
    __half* wt;  cudaGetSymbolAddress((void**)&wt,  g_wt);
    __half* wrt; cudaGetSymbolAddress((void**)&wrt, g_wrt);
    float* xrs;  cudaGetSymbolAddress((void**)&xrs, g_xres);

    // residual: xres = x @ W_res  (K=1024, A rows stride KTOT)
    gemm_res<<<dim3(BATCH / BM, HID / BN), THREADS, SMEM_BYTES>>>(xh, wrt, xrs);

    // gates GEMM + fused LSTM epilogue (gate-interleaved weights)
    gemm_gates<<<dim3(BATCH / BM, NTOT / BN), THREADS, SMEM_BYTES>>>(
        xh, wt, c, bg, br, xrs, out);

    (void)in_sizes; (void)n_in; (void)out_size;
}

// round 12
// speedup vs baseline: 1.1922x; 1.1922x over previous
#include <cuda_runtime.h>
#include <cuda_fp16.h>
#include <cstdint>
#include <math.h>

#define BATCH 8192
#define INDIM 1024
#define HID   2048
#define KTOT  3072
#define NTOT  8192

#define BM 128
#define BN 256
#define BK 64
#define STAGES 3
#define THREADS 256
#define A_BYTES (BM * BK * 2)               // 16384
#define B_BYTES (BN * BK * 2)               // 32768
#define STAGE_BYTES (A_BYTES + B_BYTES)     // 49152
#define SMEM_BYTES (STAGES * STAGE_BYTES)   // 147456

__device__ __half g_xh [(size_t)BATCH * KTOT];   // concat(x,h) fp16
__device__ __half g_wt [(size_t)NTOT  * KTOT];   // gates weights, rows = g*HID+h, K-major
__device__ __half g_wrt[(size_t)HID   * INDIM];  // residual weights, K-major
__device__ __half g_gates[(size_t)BATCH * NTOT]; // gate preacts (fp16 scratch)
__device__ float  g_xres [(size_t)BATCH * HID];  // residual preacts (fp32)

__device__ __forceinline__ uint32_t smem_u32(const void* p) {
    uint32_t a;
    asm("{ .reg .u64 t; cvta.to.shared.u64 t, %1; cvt.u32.u64 %0, t; }" : "=r"(a) : "l"(p));
    return a;
}
__device__ __forceinline__ uint32_t swz(uint32_t o) { return o ^ ((o >> 3) & 0x70); }
__device__ __forceinline__ void cp16(uint32_t dst, const void* src) {
    asm volatile("cp.async.cg.shared.global [%0], [%1], 16;" :: "r"(dst), "l"(src));
}
#define CP_COMMIT() asm volatile("cp.async.commit_group;" ::: "memory")
#define CP_WAIT(n)  asm volatile("cp.async.wait_group %0;" :: "n"(n) : "memory")

__device__ __forceinline__ void ldsm_x4(uint32_t* d, uint32_t addr) {
    asm volatile("ldmatrix.sync.aligned.m8n8.x4.shared.b16 {%0,%1,%2,%3}, [%4];"
        : "=r"(d[0]), "=r"(d[1]), "=r"(d[2]), "=r"(d[3]) : "r"(addr));
}
__device__ __forceinline__ void mma16816(float* c, const uint32_t* a, const uint32_t* b) {
    asm volatile(
        "mma.sync.aligned.m16n8k16.row.col.f32.f16.f16.f32 "
        "{%0,%1,%2,%3}, {%4,%5,%6,%7}, {%8,%9}, {%0,%1,%2,%3};"
        : "+f"(c[0]), "+f"(c[1]), "+f"(c[2]), "+f"(c[3])
        : "r"(a[0]), "r"(a[1]), "r"(a[2]), "r"(a[3]), "r"(b[0]), "r"(b[1]));
}

// ---------------- pre-passes ----------------
__global__ void prep_xh(const float* __restrict__ x, const float* __restrict__ h) {
    int k = blockIdx.x * 256 + threadIdx.x;
    int b = blockIdx.y;
    float v = (k < INDIM) ? x[(size_t)b * INDIM + k]
                          : h[(size_t)b * HID + (k - INDIM)];
    g_xh[(size_t)b * KTOT + k] = __float2half_rn(v);
}

// W_gates[g][k][h] -> g_wt[g*HID+h][k]  (R7 layout)
__global__ void prep_wg(const float* __restrict__ Wg) {
    __shared__ float t[32][33];
    int k0 = blockIdx.x * 32, h0 = blockIdx.y * 32, g = blockIdx.z;
    const float* src = Wg + ((size_t)g * KTOT + k0) * HID + h0;
#pragma unroll
    for (int i = 0; i < 4; i++)
        t[threadIdx.y + 8 * i][threadIdx.x] = src[(size_t)(threadIdx.y + 8 * i) * HID + threadIdx.x];
    __syncthreads();
#pragma unroll
    for (int i = 0; i < 4; i++) {
        int hh = threadIdx.y + 8 * i;
        g_wt[((size_t)(g * HID + h0 + hh)) * KTOT + k0 + threadIdx.x] =
            __float2half_rn(t[threadIdx.x][hh]);
    }
}

__global__ void prep_wr(const float* __restrict__ Wr) {
    __shared__ float t[32][33];
    int k0 = blockIdx.x * 32, h0 = blockIdx.y * 32;
    const float* src = Wr + (size_t)k0 * HID + h0;
#pragma unroll
    for (int i = 0; i < 4; i++)
        t[threadIdx.y + 8 * i][threadIdx.x] = src[(size_t)(threadIdx.y + 8 * i) * HID + threadIdx.x];
    __syncthreads();
#pragma unroll
    for (int i = 0; i < 4; i++) {
        int hh = threadIdx.y + 8 * i;
        g_wrt[((size_t)(h0 + hh)) * INDIM + k0 + threadIdx.x] =
            __float2half_rn(t[threadIdx.x][hh]);
    }
}

// ---------------- GEMM: C[m][n] = sum_k A[m][k] * Bw[n][k] ----------------
__device__ __forceinline__ void load_stage(uint32_t sA, uint32_t sB,
                                           const __half* __restrict__ A,
                                           const __half* __restrict__ Bw,
                                           int m0, int n0, int k0,
                                           int lda, int ldb, int tid) {
#pragma unroll
    for (int it = 0; it < 4; it++) {             // A: 128 rows x 8 x 16B
        int i = tid + it * THREADS;
        int r = i >> 3, cg = i & 7;
        uint32_t sw = swz((uint32_t)(r * 128 + cg * 16));
        cp16(sA + sw, A + (size_t)(m0 + r) * lda + k0 + cg * 8);
    }
#pragma unroll
    for (int it = 0; it < 8; it++) {             // B: 256 rows x 8 x 16B
        int i = tid + it * THREADS;
        int r = i >> 3, cg = i & 7;
        uint32_t sw = swz((uint32_t)(r * 128 + cg * 16));
        cp16(sB + sw, Bw + (size_t)(n0 + r) * ldb + k0 + cg * 8);
    }
}

__global__ void __launch_bounds__(THREADS, 1)
gemm_nt(const __half* __restrict__ A, const __half* __restrict__ Bw,
        __half* __restrict__ Ch, float* __restrict__ Cf,
        int K, int lda, int ldC) {
    extern __shared__ char smem[];
    uint32_t sb = smem_u32(smem);
    const int tid = threadIdx.x, lane = tid & 31, wid = tid >> 5;
    const int wm = wid & 1;                 // 2 warps along M (64 rows each)
    const int wn = wid >> 1;                // 4 warps along N (64 cols each)
    const int m0 = blockIdx.x * BM;
    const int n0 = blockIdx.y * BN;
    const int nch = K / BK;

    float acc[4][8][4];
#pragma unroll
    for (int mi = 0; mi < 4; mi++)
#pragma unroll
        for (int ni = 0; ni < 8; ni++)
#pragma unroll
            for (int e = 0; e < 4; e++) acc[mi][ni][e] = 0.0f;

#pragma unroll
    for (int s = 0; s < STAGES - 1; s++) {
        load_stage(sb + s * STAGE_BYTES, sb + s * STAGE_BYTES + A_BYTES,
                   A, Bw, m0, n0, s * BK, lda, K, tid);
        CP_COMMIT();
    }

    for (int c = 0; c < nch; c++) {
        CP_WAIT(STAGES - 2);
        __syncthreads();

        int cl = c + STAGES - 1;
        if (cl < nch) {
            int s = cl % STAGES;
            load_stage(sb + s * STAGE_BYTES, sb + s * STAGE_BYTES + A_BYTES,
                       A, Bw, m0, n0, cl * BK, lda, K, tid);
        }
        CP_COMMIT();

        uint32_t sA = sb + (c % STAGES) * STAGE_BYTES;
        uint32_t sB = sA + A_BYTES;

#pragma unroll
        for (int ks = 0; ks < 4; ks++) {
            uint32_t af[4][4];
            {
                int ra = lane & 15;
                int kg = ks * 2 + (lane >> 4);
#pragma unroll
                for (int mi = 0; mi < 4; mi++) {
                    uint32_t off = (uint32_t)((wm * 64 + mi * 16 + ra) * 128 + kg * 16);
                    ldsm_x4(af[mi], sA + swz(off));
                }
            }
            uint32_t bf[8][2];
            {
                int rb = (lane & 7) + ((lane >> 4) << 3);
                int kg = ks * 2 + ((lane >> 3) & 1);
#pragma unroll
                for (int nq = 0; nq < 4; nq++) {
                    uint32_t t[4];
                    uint32_t off = (uint32_t)((wn * 64 + nq * 16 + rb) * 128 + kg * 16);
                    ldsm_x4(t, sB + swz(off));
                    bf[nq * 2][0] = t[0]; bf[nq * 2][1] = t[1];
                    bf[nq * 2 + 1][0] = t[2]; bf[nq * 2 + 1][1] = t[3];
                }
            }
#pragma unroll
            for (int mi = 0; mi < 4; mi++)
#pragma unroll
                for (int ni = 0; ni < 8; ni++)
                    mma16816(acc[mi][ni], af[mi], bf[ni]);
        }
    }

    const int gid = lane >> 2, tq = lane & 3;
    if (Ch != nullptr) {
        // fp16 store (gates scratch)
#pragma unroll
        for (int mi = 0; mi < 4; mi++) {
#pragma unroll
            for (int ni = 0; ni < 8; ni++) {
                int m = m0 + wm * 64 + mi * 16 + gid;
                int n = n0 + wn * 64 + ni * 8 + tq * 2;
                *(__half2*)&Ch[(size_t)m * ldC + n] =
                    __floats2half2_rn(acc[mi][ni][0], acc[mi][ni][1]);
                *(__half2*)&Ch[(size_t)(m + 8) * ldC + n] =
                    __floats2half2_rn(acc[mi][ni][2], acc[mi][ni][3]);
            }
        }
    } else {
        // fp32 store (residual scratch)
#pragma unroll
        for (int mi = 0; mi < 4; mi++) {
#pragma unroll
            for (int ni = 0; ni < 8; ni++) {
                int m = m0 + wm * 64 + mi * 16 + gid;
                int n = n0 + wn * 64 + ni * 8 + tq * 2;
                *(float2*)&Cf[(size_t)m * ldC + n]       = make_float2(acc[mi][ni][0], acc[mi][ni][1]);
                *(float2*)&Cf[(size_t)(m + 8) * ldC + n] = make_float2(acc[mi][ni][2], acc[mi][ni][3]);
            }
        }
    }
}

// ---------------- elementwise LSTM epilogue (2 cells / thread) ----------------
__global__ void lstm_epilogue(const float* __restrict__ c_prev,
                              const float* __restrict__ bg,
                              const float* __restrict__ br,
                              float* __restrict__ out) {
    int hcol = (blockIdx.x * 256 + threadIdx.x) * 2;   // grid.x = HID/512 = 4
    int b = blockIdx.y;
    const __half* grow = g_gates + (size_t)b * NTOT;

    float2 pi = __half22float2(*(const __half2*)&grow[hcol]);
    float2 pf = __half22float2(*(const __half2*)&grow[HID + hcol]);
    float2 po = __half22float2(*(const __half2*)&grow[2 * HID + hcol]);
    float2 pc = __half22float2(*(const __half2*)&grow[3 * HID + hcol]);

    float2 bi = *(const float2*)&bg[hcol];
    float2 bf = *(const float2*)&bg[2048 + hcol];
    float2 bo = *(const float2*)&bg[4096 + hcol];
    float2 bc = *(const float2*)&bg[6144 + hcol];

    float2 cp = *(const float2*)&c_prev[(size_t)b * HID + hcol];
    float2 xr = *(const float2*)&g_xres[(size_t)b * HID + hcol];
    float2 brv = *(const float2*)&br[hcol];

    float2 ht, ct;
    {
        float iv = 1.0f / (1.0f + __expf(-(pi.x + bi.x)));
        float fv = 1.0f / (1.0f + __expf(-(pf.x + bf.x)));
        float ov = 1.0f / (1.0f + __expf(-(po.x + bo.x)));
        float ch = tanhf(pc.x + bc.x);
        ct.x = fv * cp.x + iv * ch;
        ht.x = ov * tanhf(ct.x) + xr.x + brv.x;
    }
    {
        float iv = 1.0f / (1.0f + __expf(-(pi.y + bi.y)));
        float fv = 1.0f / (1.0f + __expf(-(pf.y + bf.y)));
        float ov = 1.0f / (1.0f + __expf(-(po.y + bo.y)));
        float ch = tanhf(pc.y + bc.y);
        ct.y = fv * cp.y + iv * ch;
        ht.y = ov * tanhf(ct.y) + xr.y + brv.y;
    }

    *(float2*)&out[(size_t)b * HID + hcol] = ht;
    *(float2*)&out[(size_t)BATCH * HID + (size_t)b * HID + hcol] = ct;
}

extern "C" void kernel_launch(void* const* d_in, const int* in_sizes, int n_in,
                              void* d_out, int out_size) {
    const float* x  = (const float*)d_in[0];
    const float* h  = (const float*)d_in[1];
    const float* c  = (const float*)d_in[2];
    const float* Wg = (const float*)d_in[3];
    const float* bg = (const float*)d_in[4];
    const float* Wr = (const float*)d_in[5];
    const float* br = (const float*)d_in[6];
    float* out = (float*)d_out;

    prep_xh<<<dim3(KTOT / 256, BATCH), 256>>>(x, h);
    prep_wg<<<dim3(KTOT / 32, HID / 32, 4), dim3(32, 8)>>>(Wg);
    prep_wr<<<dim3(INDIM / 32, HID / 32), dim3(32, 8)>>>(Wr);

    cudaFuncSetAttribute(gemm_nt, cudaFuncAttributeMaxDynamicSharedMemorySize, SMEM_BYTES);

    __half* xh;  cudaGetSymbolAddress((void**)&xh,  g_xh);
    __half* wt;  cudaGetSymbolAddress((void**)&wt,  g_wt);
    __half* wrt; cudaGetSymbolAddress((void**)&wrt, g_wrt);
    __half* gts; cudaGetSymbolAddress((void**)&gts, g_gates);
    float* xrs;  cudaGetSymbolAddress((void**)&xrs, g_xres);

    // gates: [8192 x 3072] x [8192 x 3072]^T -> fp16 [8192 x 8192]
    gemm_nt<<<dim3(BATCH / BM, NTOT / BN), THREADS, SMEM_BYTES>>>(
        xh, wt, gts, nullptr, KTOT, KTOT, NTOT);
    // residual: K = INDIM, A rows stride KTOT -> fp32 [8192 x 2048]
    gemm_nt<<<dim3(BATCH / BM, HID / BN), THREADS, SMEM_BYTES>>>(
        xh, wrt, nullptr, xrs, INDIM, KTOT, HID);

    lstm_epilogue<<<dim3(HID / 512, BATCH), 256>>>(c, bg, br, out);

    (void)in_sizes; (void)n_in; (void)out_size;
}

// round 13
// speedup vs baseline: 1.3243x; 1.1108x over previous
#include <cuda_runtime.h>
#include <cuda_fp16.h>
#include <cstdint>
#include <math.h>

#define BATCH 8192
#define INDIM 1024
#define HID   2048
#define KTOT  3072
#define NTOT  8192

#define BM 128
#define BN 128
#define BK 64
#define STAGES 3
#define THREADS 128
#define A_BYTES (BM * BK * 2)               // 16384
#define B_BYTES (BN * BK * 2)               // 16384
#define STAGE_BYTES (A_BYTES + B_BYTES)     // 32768
#define SMEM_BYTES (STAGES * STAGE_BYTES)   // 98304 (2 CTAs/SM -> 192KB)

__device__ __half g_xh [(size_t)BATCH * KTOT];   // concat(x,h) fp16
__device__ __half g_wt [(size_t)NTOT  * KTOT];   // gates weights, rows = g*HID+h, K-major
__device__ __half g_wrt[(size_t)HID   * INDIM];  // residual weights, K-major
__device__ __half g_gates[(size_t)BATCH * NTOT]; // gate preacts (fp16 scratch)
__device__ float  g_xres [(size_t)BATCH * HID];  // residual preacts (fp32)

__device__ __forceinline__ uint32_t smem_u32(const void* p) {
    uint32_t a;
    asm("{ .reg .u64 t; cvta.to.shared.u64 t, %1; cvt.u32.u64 %0, t; }" : "=r"(a) : "l"(p));
    return a;
}
__device__ __forceinline__ uint32_t swz(uint32_t o) { return o ^ ((o >> 3) & 0x70); }
__device__ __forceinline__ void cp16(uint32_t dst, const void* src) {
    asm volatile("cp.async.cg.shared.global [%0], [%1], 16;" :: "r"(dst), "l"(src));
}
#define CP_COMMIT() asm volatile("cp.async.commit_group;" ::: "memory")
#define CP_WAIT(n)  asm volatile("cp.async.wait_group %0;" :: "n"(n) : "memory")

__device__ __forceinline__ void ldsm_x4(uint32_t* d, uint32_t addr) {
    asm volatile("ldmatrix.sync.aligned.m8n8.x4.shared.b16 {%0,%1,%2,%3}, [%4];"
        : "=r"(d[0]), "=r"(d[1]), "=r"(d[2]), "=r"(d[3]) : "r"(addr));
}
__device__ __forceinline__ void mma16816(float* c, const uint32_t* a, const uint32_t* b) {
    asm volatile(
        "mma.sync.aligned.m16n8k16.row.col.f32.f16.f16.f32 "
        "{%0,%1,%2,%3}, {%4,%5,%6,%7}, {%8,%9}, {%0,%1,%2,%3};"
        : "+f"(c[0]), "+f"(c[1]), "+f"(c[2]), "+f"(c[3])
        : "r"(a[0]), "r"(a[1]), "r"(a[2]), "r"(a[3]), "r"(b[0]), "r"(b[1]));
}

// ---------------- pre-passes ----------------
__global__ void prep_xh(const float* __restrict__ x, const float* __restrict__ h) {
    int k = blockIdx.x * 256 + threadIdx.x;
    int b = blockIdx.y;
    float v = (k < INDIM) ? x[(size_t)b * INDIM + k]
                          : h[(size_t)b * HID + (k - INDIM)];
    g_xh[(size_t)b * KTOT + k] = __float2half_rn(v);
}

// W_gates[g][k][h] -> g_wt[g*HID+h][k]
__global__ void prep_wg(const float* __restrict__ Wg) {
    __shared__ float t[32][33];
    int k0 = blockIdx.x * 32, h0 = blockIdx.y * 32, g = blockIdx.z;
    const float* src = Wg + ((size_t)g * KTOT + k0) * HID + h0;
#pragma unroll
    for (int i = 0; i < 4; i++)
        t[threadIdx.y + 8 * i][threadIdx.x] = src[(size_t)(threadIdx.y + 8 * i) * HID + threadIdx.x];
    __syncthreads();
#pragma unroll
    for (int i = 0; i < 4; i++) {
        int hh = threadIdx.y + 8 * i;
        g_wt[((size_t)(g * HID + h0 + hh)) * KTOT + k0 + threadIdx.x] =
            __float2half_rn(t[threadIdx.x][hh]);
    }
}

__global__ void prep_wr(const float* __restrict__ Wr) {
    __shared__ float t[32][33];
    int k0 = blockIdx.x * 32, h0 = blockIdx.y * 32;
    const float* src = Wr + (size_t)k0 * HID + h0;
#pragma unroll
    for (int i = 0; i < 4; i++)
        t[threadIdx.y + 8 * i][threadIdx.x] = src[(size_t)(threadIdx.y + 8 * i) * HID + threadIdx.x];
    __syncthreads();
#pragma unroll
    for (int i = 0; i < 4; i++) {
        int hh = threadIdx.y + 8 * i;
        g_wrt[((size_t)(h0 + hh)) * INDIM + k0 + threadIdx.x] =
            __float2half_rn(t[threadIdx.x][hh]);
    }
}

// ---------------- GEMM: C[m][n] = sum_k A[m][k] * Bw[n][k] ----------------
__device__ __forceinline__ void load_stage(uint32_t sA, uint32_t sB,
                                           const __half* __restrict__ A,
                                           const __half* __restrict__ Bw,
                                           int m0, int n0, int k0,
                                           int lda, int ldb, int tid) {
#pragma unroll
    for (int it = 0; it < 8; it++) {             // A: 128 rows x 8 x 16B = 1024 ops
        int i = tid + it * THREADS;
        int r = i >> 3, cg = i & 7;
        uint32_t sw = swz((uint32_t)(r * 128 + cg * 16));
        cp16(sA + sw, A + (size_t)(m0 + r) * lda + k0 + cg * 8);
    }
#pragma unroll
    for (int it = 0; it < 8; it++) {             // B: 128 rows x 8 x 16B = 1024 ops
        int i = tid + it * THREADS;
        int r = i >> 3, cg = i & 7;
        uint32_t sw = swz((uint32_t)(r * 128 + cg * 16));
        cp16(sB + sw, Bw + (size_t)(n0 + r) * ldb + k0 + cg * 8);
    }
}

__global__ void __launch_bounds__(THREADS, 2)
gemm_nt(const __half* __restrict__ A, const __half* __restrict__ Bw,
        __half* __restrict__ Ch, float* __restrict__ Cf,
        int K, int lda, int ldC) {
    extern __shared__ char smem[];
    uint32_t sb = smem_u32(smem);
    const int tid = threadIdx.x, lane = tid & 31, wid = tid >> 5;
    const int wm = wid & 1;                 // 2 warps along M (64 rows each)
    const int wn = wid >> 1;                // 2 warps along N (64 cols each)
    const int m0 = blockIdx.x * BM;
    const int n0 = blockIdx.y * BN;
    const int nch = K / BK;

    float acc[4][8][4];
#pragma unroll
    for (int mi = 0; mi < 4; mi++)
#pragma unroll
        for (int ni = 0; ni < 8; ni++)
#pragma unroll
            for (int e = 0; e < 4; e++) acc[mi][ni][e] = 0.0f;

#pragma unroll
    for (int s = 0; s < STAGES - 1; s++) {
        load_stage(sb + s * STAGE_BYTES, sb + s * STAGE_BYTES + A_BYTES,
                   A, Bw, m0, n0, s * BK, lda, K, tid);
        CP_COMMIT();
    }

    for (int c = 0; c < nch; c++) {
        CP_WAIT(STAGES - 2);
        __syncthreads();

        int cl = c + STAGES - 1;
        if (cl < nch) {
            int s = cl % STAGES;
            load_stage(sb + s * STAGE_BYTES, sb + s * STAGE_BYTES + A_BYTES,
                       A, Bw, m0, n0, cl * BK, lda, K, tid);
        }
        CP_COMMIT();

        uint32_t sA = sb + (c % STAGES) * STAGE_BYTES;
        uint32_t sB = sA + A_BYTES;

#pragma unroll
        for (int ks = 0; ks < 4; ks++) {
            uint32_t af[4][4];
            {
                int ra = lane & 15;
                int kg = ks * 2 + (lane >> 4);
#pragma unroll
                for (int mi = 0; mi < 4; mi++) {
                    uint32_t off = (uint32_t)((wm * 64 + mi * 16 + ra) * 128 + kg * 16);
                    ldsm_x4(af[mi], sA + swz(off));
                }
            }
            uint32_t bf[8][2];
            {
                int rb = (lane & 7) + ((lane >> 4) << 3);
                int kg = ks * 2 + ((lane >> 3) & 1);
#pragma unroll
                for (int nq = 0; nq < 4; nq++) {
                    uint32_t t[4];
                    uint32_t off = (uint32_t)((wn * 64 + nq * 16 + rb) * 128 + kg * 16);
                    ldsm_x4(t, sB + swz(off));
                    bf[nq * 2][0] = t[0]; bf[nq * 2][1] = t[1];
                    bf[nq * 2 + 1][0] = t[2]; bf[nq * 2 + 1][1] = t[3];
                }
            }
#pragma unroll
            for (int mi = 0; mi < 4; mi++)
#pragma unroll
                for (int ni = 0; ni < 8; ni++)
                    mma16816(acc[mi][ni], af[mi], bf[ni]);
        }
    }

    const int gid = lane >> 2, tq = lane & 3;
    if (Ch != nullptr) {
        // fp16 store (gates scratch)
#pragma unroll
        for (int mi = 0; mi < 4; mi++) {
#pragma unroll
            for (int ni = 0; ni < 8; ni++) {
                int m = m0 + wm * 64 + mi * 16 + gid;
                int n = n0 + wn * 64 + ni * 8 + tq * 2;
                *(__half2*)&Ch[(size_t)m * ldC + n] =
                    __floats2half2_rn(acc[mi][ni][0], acc[mi][ni][1]);
                *(__half2*)&Ch[(size_t)(m + 8) * ldC + n] =
                    __floats2half2_rn(acc[mi][ni][2], acc[mi][ni][3]);
            }
        }
    } else {
        // fp32 store (residual scratch)
#pragma unroll
        for (int mi = 0; mi < 4; mi++) {
#pragma unroll
            for (int ni = 0; ni < 8; ni++) {
                int m = m0 + wm * 64 + mi * 16 + gid;
                int n = n0 + wn * 64 + ni * 8 + tq * 2;
                *(float2*)&Cf[(size_t)m * ldC + n]       = make_float2(acc[mi][ni][0], acc[mi][ni][1]);
                *(float2*)&Cf[(size_t)(m + 8) * ldC + n] = make_float2(acc[mi][ni][2], acc[mi][ni][3]);
            }
        }
    }
}

// ---------------- elementwise LSTM epilogue (2 cells / thread) ----------------
__global__ void lstm_epilogue(const float* __restrict__ c_prev,
                              const float* __restrict__ bg,
                              const float* __restrict__ br,
                              float* __restrict__ out) {
    int hcol = (blockIdx.x * 256 + threadIdx.x) * 2;   // grid.x = HID/512 = 4
    int b = blockIdx.y;
    const __half* grow = g_gates + (size_t)b * NTOT;

    float2 pi = __half22float2(*(const __half2*)&grow[hcol]);
    float2 pf = __half22float2(*(const __half2*)&grow[HID + hcol]);
    float2 po = __half22float2(*(const __half2*)&grow[2 * HID + hcol]);
    float2 pc = __half22float2(*(const __half2*)&grow[3 * HID + hcol]);

    float2 bi = *(const float2*)&bg[hcol];
    float2 bf = *(const float2*)&bg[2048 + hcol];
    float2 bo = *(const float2*)&bg[4096 + hcol];
    float2 bc = *(const float2*)&bg[6144 + hcol];

    float2 cp = *(const float2*)&c_prev[(size_t)b * HID + hcol];
    float2 xr = *(const float2*)&g_xres[(size_t)b * HID + hcol];
    float2 brv = *(const float2*)&br[hcol];

    float2 ht, ct;
    {
        float iv = 1.0f / (1.0f + __expf(-(pi.x + bi.x)));
        float fv = 1.0f / (1.0f + __expf(-(pf.x + bf.x)));
        float ov = 1.0f / (1.0f + __expf(-(po.x + bo.x)));
        float ch = tanhf(pc.x + bc.x);
        ct.x = fv * cp.x + iv * ch;
        ht.x = ov * tanhf(ct.x) + xr.x + brv.x;
    }
    {
        float iv = 1.0f / (1.0f + __expf(-(pi.y + bi.y)));
        float fv = 1.0f / (1.0f + __expf(-(pf.y + bf.y)));
        float ov = 1.0f / (1.0f + __expf(-(po.y + bo.y)));
        float ch = tanhf(pc.y + bc.y);
        ct.y = fv * cp.y + iv * ch;
        ht.y = ov * tanhf(ct.y) + xr.y + brv.y;
    }

    *(float2*)&out[(size_t)b * HID + hcol] = ht;
    *(float2*)&out[(size_t)BATCH * HID + (size_t)b * HID + hcol] = ct;
}

extern "C" void kernel_launch(void* const* d_in, const int* in_sizes, int n_in,
                              void* d_out, int out_size) {
    const float* x  = (const float*)d_in[0];
    const float* h  = (const float*)d_in[1];
    const float* c  = (const float*)d_in[2];
    const float* Wg = (const float*)d_in[3];
    const float* bg = (const float*)d_in[4];
    const float* Wr = (const float*)d_in[5];
    const float* br = (const float*)d_in[6];
    float* out = (float*)d_out;

    prep_xh<<<dim3(KTOT / 256, BATCH), 256>>>(x, h);
    prep_wg<<<dim3(KTOT / 32, HID / 32, 4), dim3(32, 8)>>>(Wg);
    prep_wr<<<dim3(INDIM / 32, HID / 32), dim3(32, 8)>>>(Wr);

    cudaFuncSetAttribute(gemm_nt, cudaFuncAttributeMaxDynamicSharedMemorySize, SMEM_BYTES);

    __half* xh;  cudaGetSymbolAddress((void**)&xh,  g_xh);
    __half* wt;  cudaGetSymbolAddress((void**)&wt,  g_wt);
    __half* wrt; cudaGetSymbolAddress((void**)&wrt, g_wrt);
    __half* gts; cudaGetSymbolAddress((void**)&gts, g_gates);
    float* xrs;  cudaGetSymbolAddress((void**)&xrs, g_xres);

    // gates: [8192 x 3072] x [8192 x 3072]^T -> fp16 [8192 x 8192]
    gemm_nt<<<dim3(BATCH / BM, NTOT / BN), THREADS, SMEM_BYTES>>>(
        xh, wt, gts, nullptr, KTOT, KTOT, NTOT);
    // residual: K = INDIM, A rows stride KTOT -> fp32 [8192 x 2048]
    gemm_nt<<<dim3(BATCH / BM, HID / BN), THREADS, SMEM_BYTES>>>(
        xh, wrt, nullptr, xrs, INDIM, KTOT, HID);

    lstm_epilogue<<<dim3(HID / 512, BATCH), 256>>>(c, bg, br, out);

    (void)in_sizes; (void)n_in; (void)out_size;
}